// round 10
// baseline (speedup 1.0000x reference)
#include <cuda_runtime.h>
#include <cstdint>

// Fused batched GCN, one CTA per graph (512 x 100 nodes, deg 16), fp32.
// 512 threads / 16 warps. Warp-level fusion: each warp owns rows
// {warp + 16*i, i<7} and runs agg1 -> GEMM1 -> GEMM2 on them with only
// __syncwarp()s in between (no CTA barrier until the full t matrix is needed
// by aggregation 2). h1 gets its own buffer so W1 stays valid for laggards.
// GEMMs use packed fma.rn.f32x2 over k. Heads: softmax over length-1 token
// == 1 -> Z=(x@Wv^T)@Wo^T; Wq/Wk dead.

#define NPG   100
#define DEG   16
#define DIN   100
#define H1D   100
#define DG    20
#define P2D   200
#define P3D   100

#define PX    100   // feat pitch (floats)
#define PA    106   // pitch of A / W1 / h1 tiles (conflict-free LDS.64 phases)
#define PT    21    // pitch of 20-wide buffers (odd -> conflict-free)

// ---- shared memory layout (float element offsets) ----
#define OFF_X     0                      // 10000   feat
#define OFF_A     (OFF_X   + 10000)      // 11872   agg1 (112*106)
#define OFF_W1    (OFF_A   + 11872)      // 10600   W1 (100*106)
#define OFF_H1    (OFF_W1  + 10600)      // 11872   h1 (112*106)
#define OFF_W2    (OFF_H1  + 11872)      // 2120    W2 (20*106)
#define OFF_T     (OFF_W2  + 2120)       // 2100    t = h1@W2^T (100*21)
#define OFF_T2    (OFF_T   + 2100)       // 2100    agg2
#define OFF_E     (OFF_T2  + 2100)       // 1600 ints
#define OFF_SF    (OFF_E   + 1600)       // 200
#define OFF_X3    (OFF_SF  + 200)        // 100
#define OFF_PART  (OFF_X3  + 100)        // 16*20
#define OFF_VP2   (OFF_PART + 320)       // 512
#define OFF_VP3   (OFF_VP2 + 512)        // 512
#define OFF_VV    (OFF_VP3 + 512)        // 64
#define OFF_HG2   (OFF_VV  + 64)         // 20
#define OFF_O10   (OFF_HG2 + 20)         // 12
#define SMEM_ELEMS (OFF_O10 + 16)
#define SMEM_BYTES (SMEM_ELEMS * 4)      // ~216 KB, 1 CTA/SM

typedef unsigned long long u64;

static __device__ __forceinline__ void ffma2(u64& d, u64 a, u64 b) {
    asm("fma.rn.f32x2 %0, %1, %2, %0;" : "+l"(d) : "l"(a), "l"(b));
}
static __device__ __forceinline__ void fadd2(u64& d, u64 a) {
    asm("add.rn.f32x2 %0, %0, %1;" : "+l"(d) : "l"(a));
}
static __device__ __forceinline__ void fmul2(u64& d, u64 a) {
    asm("mul.rn.f32x2 %0, %0, %1;" : "+l"(d) : "l"(a));
}
static __device__ __forceinline__ void lds_v2u64(u64& a, u64& b, const float* p) {
    asm("ld.shared.v2.u64 {%0,%1}, [%2];" : "=l"(a), "=l"(b) : "l"(__cvta_generic_to_shared(p)));
}
static __device__ __forceinline__ float hsum2(u64 v) {
    float lo = __uint_as_float((unsigned)(v & 0xffffffffu));
    float hi = __uint_as_float((unsigned)(v >> 32));
    return lo + hi;
}

__global__ __launch_bounds__(512, 1)
void net_kernel(const float* __restrict__ feat,
                const int*   __restrict__ edge_src,
                const float* __restrict__ self_feat,
                const float* __restrict__ x3d,
                const float* __restrict__ W1,  const float* __restrict__ b1,
                const float* __restrict__ W2,  const float* __restrict__ b2,
                const float* __restrict__ Wv2, const float* __restrict__ Wo2,
                const float* __restrict__ g2,  const float* __restrict__ be2,
                const float* __restrict__ Wv3, const float* __restrict__ Wo3,
                const float* __restrict__ g3,  const float* __restrict__ be3,
                const float* __restrict__ Wf1, const float* __restrict__ bf1,
                const float* __restrict__ Wf2, const float* __restrict__ bf2,
                float* __restrict__ out)
{
    extern __shared__ float sm[];
    float* sX   = sm + OFF_X;
    float* sA   = sm + OFF_A;
    float* sW1  = sm + OFF_W1;
    float* sH1  = sm + OFF_H1;
    float* sW2  = sm + OFF_W2;
    float* sT   = sm + OFF_T;
    float* sT2  = sm + OFF_T2;
    int*   sEdge= (int*)(sm + OFF_E);
    float* sSf  = sm + OFF_SF;
    float* sX3  = sm + OFF_X3;
    float* sPart= sm + OFF_PART;
    float* sVp2 = sm + OFF_VP2;
    float* sVp3 = sm + OFF_VP3;
    float* sVv  = sm + OFF_VV;
    float* sHg2 = sm + OFF_HG2;
    float* sO10 = sm + OFF_O10;

    const int g    = blockIdx.x;
    const int tid  = threadIdx.x;
    const int warp = tid >> 5;
    const int lane = tid & 31;

    // ---------------- Phase 1: stage inputs ----------------
    for (int i = tid; i < NPG * DEG; i += 512)
        sEdge[i] = edge_src[g * (NPG * DEG) + i] - g * NPG;
    {
        const float4* fsrc = (const float4*)(feat + (size_t)g * NPG * DIN);
        for (int i4 = tid; i4 < (NPG * DIN) / 4; i4 += 512)
            *(float4*)&sX[i4 * 4] = fsrc[i4];           // pitch 100 == DIN
    }
    for (int idx = tid; idx < H1D * (DIN / 2); idx += 512) {
        int o = idx / 50, kp = idx - o * 50;
        *(u64*)&sW1[o * PA + 2 * kp] = *(const u64*)&W1[o * DIN + 2 * kp];
    }
    for (int idx = tid; idx < DG * (H1D / 2); idx += 512) {
        int o = idx / 50, kp = idx - o * 50;
        *(u64*)&sW2[o * PA + 2 * kp] = *(const u64*)&W2[o * H1D + 2 * kp];
    }
    for (int i = tid; i < P2D; i += 512) sSf[i] = self_feat[g * P2D + i];
    for (int i = tid; i < P3D; i += 512) sX3[i] = x3d[g * P3D + i];
    __syncthreads();

    // ============ Fused per-warp pipeline: agg1 -> GEMM1 -> GEMM2 ============
    // Rows owned by this warp: r_i = warp + 16*i (i < 7; r_i < 100).

    // ---- agg1: mean of 16 neighbors, 100 dims, into sA (own rows) ----
    if (lane < 25) {
        #pragma unroll
        for (int i = 0; i < 7; ++i) {
            int n = warp + 16 * i;
            if (n < NPG) {
                u64 acc0 = 0ull, acc1 = 0ull;
                int base = n * DEG;
                #pragma unroll
                for (int j = 0; j < DEG; ++j) {
                    int s = sEdge[base + j];
                    u64 v0, v1;
                    lds_v2u64(v0, v1, &sX[s * PX + (lane << 2)]);
                    fadd2(acc0, v0);
                    fadd2(acc1, v1);
                }
                const u64 inv2 = 0x3D8000003D800000ull;   // (1/16, 1/16)
                fmul2(acc0, inv2);
                fmul2(acc1, inv2);
                int c = lane << 2;
                *(u64*)&sA[n * PA + c]     = acc0;
                *(u64*)&sA[n * PA + c + 2] = acc1;
            }
        }
    }
    __syncwarp();

    // ---- GEMM1: h1 = relu(A @ W1^T + b1), 7 rows x 4 cols per thread ----
    {
        int wrow[4];
        #pragma unroll
        for (int j = 0; j < 4; ++j) {
            int c = lane + 32 * j;
            wrow[j] = (c < H1D) ? c : 0;
        }
        u64 acc[7][4];
        #pragma unroll
        for (int i = 0; i < 7; ++i)
            #pragma unroll
            for (int j = 0; j < 4; ++j) acc[i][j] = 0ull;

        #pragma unroll 2
        for (int kp = 0; kp < DIN / 2; ++kp) {
            const int k = kp * 2;
            u64 a2[7], w2[4];
            #pragma unroll
            for (int i = 0; i < 7; ++i)           // broadcast (warp-uniform)
                a2[i] = *(const u64*)&sA[(warp + 16 * i) * PA + k];
            #pragma unroll
            for (int j = 0; j < 4; ++j)
                w2[j] = *(const u64*)&sW1[wrow[j] * PA + k];
            #pragma unroll
            for (int i = 0; i < 7; ++i)
                #pragma unroll
                for (int j = 0; j < 4; ++j) ffma2(acc[i][j], a2[i], w2[j]);
        }

        float bb[4];
        #pragma unroll
        for (int j = 0; j < 4; ++j) {
            int c = lane + 32 * j;
            bb[j] = (c < H1D) ? b1[c] : 0.f;
        }
        #pragma unroll
        for (int i = 0; i < 7; ++i) {
            int r = warp + 16 * i;
            if (r < NPG) {
                #pragma unroll
                for (int j = 0; j < 4; ++j) {
                    int c = lane + 32 * j;
                    if (c < H1D)
                        sH1[r * PA + c] = fmaxf(hsum2(acc[i][j]) + bb[j], 0.f);
                }
            }
        }
    }
    __syncwarp();   // own h1 rows visible to own warp

    // ---- GEMM2: t = h1 @ W2^T (pre-bias), same rows, col = lane ----
    {
        const int wrow = (lane < DG) ? lane : 0;
        u64 acc[7];
        #pragma unroll
        for (int i = 0; i < 7; ++i) acc[i] = 0ull;

        #pragma unroll 2
        for (int kp = 0; kp < H1D / 2; ++kp) {
            const int k = kp * 2;
            u64 w = *(const u64*)&sW2[wrow * PA + k];
            #pragma unroll
            for (int i = 0; i < 7; ++i) {         // broadcast own h1 rows
                u64 a = *(const u64*)&sH1[(warp + 16 * i) * PA + k];
                ffma2(acc[i], a, w);
            }
        }
        if (lane < DG) {
            #pragma unroll
            for (int i = 0; i < 7; ++i) {
                int r = warp + 16 * i;
                if (r < NPG) sT[r * PT + lane] = hsum2(acc[i]);
            }
        }
    }
    __syncthreads();   // full t matrix needed for aggregation 2

    // ---------------- agg2: mean over neighbors (20 dims) --------------------
    for (int n = warp; n < NPG; n += 16) {
        if (lane < DG) {
            float acc = 0.f;
            int base = n * DEG;
            #pragma unroll
            for (int j = 0; j < DEG; ++j)
                acc += sT[sEdge[base + j] * PT + lane];
            sT2[n * PT + lane] = acc * (1.f / DEG);
        }
    }
    __syncwarp();   // sT2 own rows re-read below by same warp

    // ---------------- hg partials + attention V partials ---------------------
    if (lane < DG) {
        float b = b2[lane];
        float acc = 0.f;
        for (int n = warp; n < NPG; n += 16)
            acc += fmaxf(sT2[n * PT + lane] + b, 0.f);
        sPart[warp * DG + lane] = acc;
    }
    {
        int j  = lane;
        int pg = warp;
        {   // v2: 200 dims in 16 chunks of 13 (clamped)
            int p0 = pg * 13, p1 = min(p0 + 13, P2D);
            float acc = 0.f;
            for (int p = p0; p < p1; ++p) acc = fmaf(Wv2[j * P2D + p], sSf[p], acc);
            sVp2[pg * 32 + j] = acc;
        }
        {   // v3: 100 dims in 16 chunks of 7 (clamped)
            int p0 = pg * 7, p1 = min(p0 + 7, P3D);
            float acc = 0.f;
            for (int p = p0; p < p1; ++p) acc = fmaf(Wv3[j * P3D + p], sX3[p], acc);
            sVp3[pg * 32 + j] = acc;
        }
    }
    __syncthreads();

    // ---------------- head (warp 0) ------------------------------------------
    if (tid < 32) {
        float v2 = 0.f, v3 = 0.f;
        #pragma unroll
        for (int pg = 0; pg < 16; ++pg) {
            v2 += sVp2[pg * 32 + lane];
            v3 += sVp3[pg * 32 + lane];
        }
        sVv[lane]      = v2;
        sVv[32 + lane] = v3;
        __syncwarp();

        float hg = 0.f, z2 = 0.f;
        if (lane < DG) {
            #pragma unroll
            for (int w = 0; w < 16; ++w) hg += sPart[w * DG + lane];
            hg *= (1.f / NPG);
            #pragma unroll
            for (int j = 0; j < 32; ++j) z2 = fmaf(Wo2[lane * 32 + j], sVv[j], z2);
        }
        float y = hg + z2;
        float t = (lane < DG) ? y : 0.f;
        #pragma unroll
        for (int o = 16; o > 0; o >>= 1) t += __shfl_xor_sync(0xffffffffu, t, o);
        float mu = t * (1.f / DG);
        float dv = (lane < DG) ? (y - mu) : 0.f;
        float t2 = dv * dv;
        #pragma unroll
        for (int o = 16; o > 0; o >>= 1) t2 += __shfl_xor_sync(0xffffffffu, t2, o);
        float inv = rsqrtf(t2 * (1.f / DG) + 1e-5f);
        float hg1 = (lane < DG) ? fmaf((y - mu) * inv, g2[lane], be2[lane]) : 0.f;

        float z3 = 0.f;
        if (lane < DG) {
            #pragma unroll
            for (int j = 0; j < 32; ++j) z3 = fmaf(Wo3[lane * 32 + j], sVv[32 + j], z3);
        }
        float y2 = hg1 + z3;
        t = (lane < DG) ? y2 : 0.f;
        #pragma unroll
        for (int o = 16; o > 0; o >>= 1) t += __shfl_xor_sync(0xffffffffu, t, o);
        mu = t * (1.f / DG);
        dv = (lane < DG) ? (y2 - mu) : 0.f;
        t2 = dv * dv;
        #pragma unroll
        for (int o = 16; o > 0; o >>= 1) t2 += __shfl_xor_sync(0xffffffffu, t2, o);
        inv = rsqrtf(t2 * (1.f / DG) + 1e-5f);
        if (lane < DG) sHg2[lane] = fmaf((y2 - mu) * inv, g3[lane], be3[lane]);
        __syncwarp();

        if (lane < 10) {
            float a = bf1[lane];
            #pragma unroll
            for (int d = 0; d < DG; ++d) a = fmaf(Wf1[lane * DG + d], sHg2[d], a);
            sO10[lane] = fmaxf(a, 0.f);
        }
        __syncwarp();

        if (lane == 0) {
            float o = bf2[0];
            #pragma unroll
            for (int i = 0; i < 10; ++i) o = fmaf(Wf2[i], sO10[i], o);
            out[g] = o;
        }
    }
}

extern "C" void kernel_launch(void* const* d_in, const int* in_sizes, int n_in,
                              void* d_out, int out_size) {
    const float* feat     = (const float*)d_in[0];
    const int*   edge_src = (const int*)  d_in[1];
    // d_in[2] = edge_dst (implicit: repeat(arange))
    const float* self_f   = (const float*)d_in[3];
    const float* x3d      = (const float*)d_in[4];
    const float* W1  = (const float*)d_in[5];
    const float* b1  = (const float*)d_in[6];
    const float* W2  = (const float*)d_in[7];
    const float* b2  = (const float*)d_in[8];
    // 9 Wq2, 10 Wk2 unused (softmax over length-1 token == 1)
    const float* Wv2 = (const float*)d_in[11];
    const float* Wo2 = (const float*)d_in[12];
    const float* g2  = (const float*)d_in[13];
    const float* be2 = (const float*)d_in[14];
    // 15 Wq3, 16 Wk3 unused
    const float* Wv3 = (const float*)d_in[17];
    const float* Wo3 = (const float*)d_in[18];
    const float* g3  = (const float*)d_in[19];
    const float* be3 = (const float*)d_in[20];
    const float* Wf1 = (const float*)d_in[21];
    const float* bf1 = (const float*)d_in[22];
    const float* Wf2 = (const float*)d_in[23];
    const float* bf2 = (const float*)d_in[24];
    float* out = (float*)d_out;

    cudaFuncSetAttribute(net_kernel, cudaFuncAttributeMaxDynamicSharedMemorySize,
                         SMEM_BYTES);
    net_kernel<<<512, 512, SMEM_BYTES>>>(feat, edge_src, self_f, x3d,
                                         W1, b1, W2, b2,
                                         Wv2, Wo2, g2, be2,
                                         Wv3, Wo3, g3, be3,
                                         Wf1, bf1, Wf2, bf2, out);
}